// round 11
// baseline (speedup 1.0000x reference)
#include <cuda_runtime.h>
#include <cstdint>

// ---------------- problem constants ----------------
#define M_TOK  16384     // BATCH * SEQ
#define DIMN   1024
#define KLR    256
#define BATCHN 4
#define SEQN   4096
#define HEADSN 16
#define DHN    64

// ---------------- scratch (device globals) ----------------
__device__ float g_Q[16384 * 1024];
__device__ float g_AO[16384 * 1024];
__device__ float g_keys[4 * 256 * 1024];
__device__ float g_vals[4 * 256 * 1024];
__device__ float g_xk[4 * 256 * 1024];
__device__ float g_xv[4 * 256 * 1024];
__device__ float g_xt[16384 * 1024];
__device__ float g_wqt[1024 * 1024];
__device__ float g_wkt[1024 * 1024];
__device__ float g_wvt[1024 * 1024];
__device__ float g_wot[1024 * 1024];
__device__ float g_pkt[4096 * 256];
__device__ float g_pvt[4096 * 256];

// ---------------- tf32 helpers ----------------
__device__ __forceinline__ float tf32r(float f) {
    uint32_t u;
    asm("cvt.rna.tf32.f32 %0, %1;" : "=r"(u) : "f"(f));
    return __uint_as_float(u);
}

__device__ __forceinline__ void mma_tf32(
    float& c0, float& c1, float& c2, float& c3,
    uint32_t a0, uint32_t a1, uint32_t a2, uint32_t a3,
    uint32_t b0, uint32_t b1)
{
    asm volatile(
        "mma.sync.aligned.m16n8k8.row.col.f32.tf32.tf32.f32 "
        "{%0,%1,%2,%3}, {%4,%5,%6,%7}, {%8,%9}, {%0,%1,%2,%3};\n"
        : "+f"(c0), "+f"(c1), "+f"(c2), "+f"(c3)
        : "r"(a0), "r"(a1), "r"(a2), "r"(a3), "r"(b0), "r"(b1));
}

__device__ __forceinline__ void cp16(uint32_t smem, const void* g) {
    asm volatile("cp.async.cg.shared.global [%0], [%1], 16;\n"
                 :: "r"(smem), "l"(g));
}
__device__ __forceinline__ void cp_commit() {
    asm volatile("cp.async.commit_group;\n");
}
__device__ __forceinline__ void cp_wait0() {
    asm volatile("cp.async.wait_group 0;\n");
}
__device__ __forceinline__ uint32_t smem_u32(const void* p) {
    return (uint32_t)__cvta_generic_to_shared(p);
}

// ---------------- prep: round to tf32 (RNA) ----------------
__global__ __launch_bounds__(256) void round_tf32_kernel(
    const float* __restrict__ in, float* __restrict__ out, int n4)
{
    int i = blockIdx.x * 256 + threadIdx.x;
    if (i < n4) {
        float4 v = ((const float4*)in)[i];
        v.x = tf32r(v.x); v.y = tf32r(v.y); v.z = tf32r(v.z); v.w = tf32r(v.w);
        ((float4*)out)[i] = v;
    }
}

// =====================================================================
// BIG NT TF32 GEMM: block 256x128, 8 warps, warp tile 64x64, BK=16.
// MMA:LDS ratio 1:1 (vs 16:24 in the small-tile kernel).
// Dynamic smem: As[2][256*20] + Bs[2][128*20] uint32 = 61440 B.
// =====================================================================
#define NTBIG_SMEM ((2 * 256 * 20 + 2 * 128 * 20) * 4)

__global__ __launch_bounds__(256) void gemm_nt_big(
    const float* __restrict__ A, const float* __restrict__ B,
    const float* __restrict__ bias, float* __restrict__ C,
    int K, int lda, int ldb, int ldc, int add_bias, int round_out)
{
    extern __shared__ uint32_t dsm[];
    uint32_t* AsB[2] = { dsm, dsm + 256 * 20 };
    uint32_t* BsB[2] = { dsm + 2 * 256 * 20, dsm + 2 * 256 * 20 + 128 * 20 };

    const int tid  = threadIdx.x;
    const int wid  = tid >> 5, lane = tid & 31;
    const int g    = lane >> 2, tig = lane & 3;
    const int wm   = wid >> 1;            // 0..3 -> 64 rows each
    const int wn   = wid & 1;             // 0..1 -> 64 cols each
    const int m0   = blockIdx.y * 256;
    const int n0   = blockIdx.x * 128;

    // staging: A row per thread (4 cp16); B row = tid>>1, half-row (2 cp16)
    const float* Ag = A + (long long)(m0 + tid) * lda;
    const int brow = tid >> 1, bch = (tid & 1) * 8;
    const float* Bg = B + (long long)(n0 + brow) * ldb + bch;

    uint32_t aDst[2], bDst[2];
#pragma unroll
    for (int b2 = 0; b2 < 2; b2++) {
        aDst[b2] = smem_u32(&AsB[b2][tid * 20]);
        bDst[b2] = smem_u32(&BsB[b2][brow * 20 + bch]);
    }

    float acc[4][8][4];
#pragma unroll
    for (int mt = 0; mt < 4; mt++)
#pragma unroll
        for (int nt = 0; nt < 8; nt++)
#pragma unroll
            for (int r = 0; r < 4; r++) acc[mt][nt][r] = 0.f;

    // prologue: stage k0=0 into buf 0
    cp16(aDst[0], Ag);          cp16(aDst[0] + 16, Ag + 4);
    cp16(aDst[0] + 32, Ag + 8); cp16(aDst[0] + 48, Ag + 12);
    cp16(bDst[0], Bg);          cp16(bDst[0] + 16, Bg + 4);
    cp_commit();

    int buf = 0;
    for (int k0 = 0; k0 < K; k0 += 16) {
        cp_wait0();
        __syncthreads();
        if (k0 + 16 < K) {
            const int nb = buf ^ 1;
            const float* An = Ag + k0 + 16;
            const float* Bn = Bg + k0 + 16;
            cp16(aDst[nb], An);          cp16(aDst[nb] + 16, An + 4);
            cp16(aDst[nb] + 32, An + 8); cp16(aDst[nb] + 48, An + 12);
            cp16(bDst[nb], Bn);          cp16(bDst[nb] + 16, Bn + 4);
            cp_commit();
        }
        const uint32_t* Ab = AsB[buf];
        const uint32_t* Bb = BsB[buf];
#pragma unroll
        for (int ks = 0; ks < 2; ks++) {
            uint32_t af[4][4], bf[8][2];
#pragma unroll
            for (int mt = 0; mt < 4; mt++) {
                int mr = wm * 64 + mt * 16 + g;
                af[mt][0] = Ab[mr * 20 + ks * 8 + tig];
                af[mt][1] = Ab[(mr + 8) * 20 + ks * 8 + tig];
                af[mt][2] = Ab[mr * 20 + ks * 8 + tig + 4];
                af[mt][3] = Ab[(mr + 8) * 20 + ks * 8 + tig + 4];
            }
#pragma unroll
            for (int nt = 0; nt < 8; nt++) {
                int nr = wn * 64 + nt * 8 + g;
                bf[nt][0] = Bb[nr * 20 + ks * 8 + tig];
                bf[nt][1] = Bb[nr * 20 + ks * 8 + tig + 4];
            }
#pragma unroll
            for (int mt = 0; mt < 4; mt++)
#pragma unroll
                for (int nt = 0; nt < 8; nt++)
                    mma_tf32(acc[mt][nt][0], acc[mt][nt][1], acc[mt][nt][2], acc[mt][nt][3],
                             af[mt][0], af[mt][1], af[mt][2], af[mt][3],
                             bf[nt][0], bf[nt][1]);
        }
        buf ^= 1;
    }

    // epilogue
#pragma unroll
    for (int nt = 0; nt < 8; nt++) {
        int col = n0 + wn * 64 + nt * 8 + tig * 2;
        float b0 = 0.f, b1 = 0.f;
        if (add_bias) { b0 = bias[col]; b1 = bias[col + 1]; }
#pragma unroll
        for (int mt = 0; mt < 4; mt++) {
            int row = m0 + wm * 64 + mt * 16 + g;
            float v00 = acc[mt][nt][0] + b0, v01 = acc[mt][nt][1] + b1;
            float v10 = acc[mt][nt][2] + b0, v11 = acc[mt][nt][3] + b1;
            if (round_out) {
                v00 = tf32r(v00); v01 = tf32r(v01);
                v10 = tf32r(v10); v11 = tf32r(v11);
            }
            *(float2*)(C + (long long)row * ldc + col) = make_float2(v00, v01);
            *(float2*)(C + (long long)(row + 8) * ldc + col) = make_float2(v10, v11);
        }
    }
}

// =====================================================================
// FUSED TN TF32 GEMM (batched z): C1 = A1^T·B, C2 = A2^T·B.
// A1=pk, A2=pv share the SAME B (x) tile -> stage x once.
// Block 64x128 per output, BK=16, warp tile 32x32. Outputs tf32-rounded.
// =====================================================================
__global__ __launch_bounds__(256) void gemm_tn2_tf32(
    const float* __restrict__ A1, const float* __restrict__ A2,
    const float* __restrict__ B,
    float* __restrict__ C1, float* __restrict__ C2,
    int P, int lda, int ldb, int ldc, long long strideB, long long strideC)
{
    B  += (long long)blockIdx.z * strideB;
    C1 += (long long)blockIdx.z * strideC;
    C2 += (long long)blockIdx.z * strideC;

    __shared__ uint32_t As1[2][16 * 72];
    __shared__ uint32_t As2[2][16 * 72];
    __shared__ uint32_t Bs[2][16 * 136];

    const int tid  = threadIdx.x;
    const int wid  = tid >> 5, lane = tid & 31;
    const int g    = lane >> 2, tig = lane & 3;
    const int wm   = wid >> 2;
    const int wn   = wid & 3;
    const int m0   = blockIdx.y * 64;
    const int n0   = blockIdx.x * 128;

    const int lp   = tid >> 4;
    const int lma  = (tid & 15) * 4;
    const int lnb  = (tid & 15) * 8;
    const float* A1g = A1 + (long long)lp * lda + m0 + lma;
    const float* A2g = A2 + (long long)lp * lda + m0 + lma;
    const float* Bg  = B  + (long long)lp * ldb + n0 + lnb;

    uint32_t s1[2], s2[2], sbv[2];
#pragma unroll
    for (int b2 = 0; b2 < 2; b2++) {
        s1[b2]  = smem_u32(&As1[b2][lp * 72 + lma]);
        s2[b2]  = smem_u32(&As2[b2][lp * 72 + lma]);
        sbv[b2] = smem_u32(&Bs[b2][lp * 136 + lnb]);
    }

    float ac1[2][4][4], ac2[2][4][4];
#pragma unroll
    for (int mt = 0; mt < 2; mt++)
#pragma unroll
        for (int nt = 0; nt < 4; nt++)
#pragma unroll
            for (int r = 0; r < 4; r++) { ac1[mt][nt][r] = 0.f; ac2[mt][nt][r] = 0.f; }

    cp16(s1[0], A1g);
    cp16(s2[0], A2g);
    cp16(sbv[0], Bg);   cp16(sbv[0] + 16, Bg + 4);
    cp_commit();

    int buf = 0;
    for (int p0 = 0; p0 < P; p0 += 16) {
        cp_wait0();
        __syncthreads();
        if (p0 + 16 < P) {
            const int nb = buf ^ 1;
            const float* A1n = A1g + (long long)(p0 + 16) * lda;
            const float* A2n = A2g + (long long)(p0 + 16) * lda;
            const float* Bn  = Bg  + (long long)(p0 + 16) * ldb;
            cp16(s1[nb], A1n);
            cp16(s2[nb], A2n);
            cp16(sbv[nb], Bn);   cp16(sbv[nb] + 16, Bn + 4);
            cp_commit();
        }
        const uint32_t* Ab1 = As1[buf];
        const uint32_t* Ab2 = As2[buf];
        const uint32_t* Bb  = Bs[buf];
#pragma unroll
        for (int ks = 0; ks < 2; ks++) {
            uint32_t f1[2][4], f2[2][4], bf[4][2];
#pragma unroll
            for (int mt = 0; mt < 2; mt++) {
                int bm = wm * 32 + mt * 16 + g;
                f1[mt][0] = Ab1[(ks * 8 + tig) * 72 + bm];
                f1[mt][1] = Ab1[(ks * 8 + tig) * 72 + bm + 8];
                f1[mt][2] = Ab1[(ks * 8 + tig + 4) * 72 + bm];
                f1[mt][3] = Ab1[(ks * 8 + tig + 4) * 72 + bm + 8];
                f2[mt][0] = Ab2[(ks * 8 + tig) * 72 + bm];
                f2[mt][1] = Ab2[(ks * 8 + tig) * 72 + bm + 8];
                f2[mt][2] = Ab2[(ks * 8 + tig + 4) * 72 + bm];
                f2[mt][3] = Ab2[(ks * 8 + tig + 4) * 72 + bm + 8];
            }
#pragma unroll
            for (int nt = 0; nt < 4; nt++) {
                int bn = wn * 32 + nt * 8 + g;
                bf[nt][0] = Bb[(ks * 8 + tig) * 136 + bn];
                bf[nt][1] = Bb[(ks * 8 + tig + 4) * 136 + bn];
            }
#pragma unroll
            for (int mt = 0; mt < 2; mt++)
#pragma unroll
                for (int nt = 0; nt < 4; nt++) {
                    mma_tf32(ac1[mt][nt][0], ac1[mt][nt][1], ac1[mt][nt][2], ac1[mt][nt][3],
                             f1[mt][0], f1[mt][1], f1[mt][2], f1[mt][3],
                             bf[nt][0], bf[nt][1]);
                    mma_tf32(ac2[mt][nt][0], ac2[mt][nt][1], ac2[mt][nt][2], ac2[mt][nt][3],
                             f2[mt][0], f2[mt][1], f2[mt][2], f2[mt][3],
                             bf[nt][0], bf[nt][1]);
                }
        }
        buf ^= 1;
    }

#pragma unroll
    for (int mt = 0; mt < 2; mt++) {
        int row = m0 + wm * 32 + mt * 16 + g;
#pragma unroll
        for (int nt = 0; nt < 4; nt++) {
            int col = n0 + wn * 32 + nt * 8 + tig * 2;
            *(float2*)(C1 + (long long)row * ldc + col) =
                make_float2(tf32r(ac1[mt][nt][0]), tf32r(ac1[mt][nt][1]));
            *(float2*)(C1 + (long long)(row + 8) * ldc + col) =
                make_float2(tf32r(ac1[mt][nt][2]), tf32r(ac1[mt][nt][3]));
            *(float2*)(C2 + (long long)row * ldc + col) =
                make_float2(tf32r(ac2[mt][nt][0]), tf32r(ac2[mt][nt][1]));
            *(float2*)(C2 + (long long)(row + 8) * ldc + col) =
                make_float2(tf32r(ac2[mt][nt][2]), tf32r(ac2[mt][nt][3]));
        }
    }
}

// =====================================================================
// NT TF32 GEMM (small keys/vals GEMMs; unchanged from R8)
// =====================================================================
__global__ __launch_bounds__(256, 2) void gemm_nt_tf32(
    const float* __restrict__ A, const float* __restrict__ B,
    const float* __restrict__ bias, float* __restrict__ C,
    int K, int lda, int ldb, int ldc, int add_bias, int round_out)
{
    __shared__ uint32_t As[2][128 * 20];
    __shared__ uint32_t Bs[2][128 * 20];

    const int tid  = threadIdx.x;
    const int wid  = tid >> 5, lane = tid & 31;
    const int g    = lane >> 2, tig = lane & 3;
    const int wm   = wid >> 2;
    const int wn   = wid & 3;
    const int m0   = blockIdx.y * 128;
    const int n0   = blockIdx.x * 128;

    const int lrow = tid >> 1;
    const int lkg  = (tid & 1) * 8;
    const float* Ag = A + (long long)(m0 + lrow) * lda + lkg;
    const float* Bg = B + (long long)(n0 + lrow) * ldb + lkg;

    const uint32_t sa0 = smem_u32(&As[0][lrow * 20 + lkg]);
    const uint32_t sa1 = smem_u32(&As[1][lrow * 20 + lkg]);
    const uint32_t sb0 = smem_u32(&Bs[0][lrow * 20 + lkg]);
    const uint32_t sb1 = smem_u32(&Bs[1][lrow * 20 + lkg]);

    float acc[4][4][4];
#pragma unroll
    for (int mt = 0; mt < 4; mt++)
#pragma unroll
        for (int nt = 0; nt < 4; nt++)
#pragma unroll
            for (int r = 0; r < 4; r++) acc[mt][nt][r] = 0.f;

    cp16(sa0, Ag);      cp16(sa0 + 16, Ag + 4);
    cp16(sb0, Bg);      cp16(sb0 + 16, Bg + 4);
    cp_commit();

    int buf = 0;
    for (int k0 = 0; k0 < K; k0 += 16) {
        cp_wait0();
        __syncthreads();
        if (k0 + 16 < K) {
            uint32_t da = buf ? sa0 : sa1;
            uint32_t db = buf ? sb0 : sb1;
            cp16(da, Ag + k0 + 16);      cp16(da + 16, Ag + k0 + 20);
            cp16(db, Bg + k0 + 16);      cp16(db + 16, Bg + k0 + 20);
            cp_commit();
        }
        const uint32_t* Ab = As[buf];
        const uint32_t* Bb = Bs[buf];
#pragma unroll
        for (int ks = 0; ks < 2; ks++) {
            uint32_t af[4][4], bf[4][2];
#pragma unroll
            for (int mt = 0; mt < 4; mt++) {
                int mr = wm * 64 + mt * 16 + g;
                af[mt][0] = Ab[mr * 20 + ks * 8 + tig];
                af[mt][1] = Ab[(mr + 8) * 20 + ks * 8 + tig];
                af[mt][2] = Ab[mr * 20 + ks * 8 + tig + 4];
                af[mt][3] = Ab[(mr + 8) * 20 + ks * 8 + tig + 4];
            }
#pragma unroll
            for (int nt = 0; nt < 4; nt++) {
                int nr = wn * 32 + nt * 8 + g;
                bf[nt][0] = Bb[nr * 20 + ks * 8 + tig];
                bf[nt][1] = Bb[nr * 20 + ks * 8 + tig + 4];
            }
#pragma unroll
            for (int mt = 0; mt < 4; mt++)
#pragma unroll
                for (int nt = 0; nt < 4; nt++)
                    mma_tf32(acc[mt][nt][0], acc[mt][nt][1], acc[mt][nt][2], acc[mt][nt][3],
                             af[mt][0], af[mt][1], af[mt][2], af[mt][3],
                             bf[nt][0], bf[nt][1]);
        }
        buf ^= 1;
    }

#pragma unroll
    for (int nt = 0; nt < 4; nt++) {
        int col = n0 + wn * 32 + nt * 8 + tig * 2;
        float b0 = 0.f, b1 = 0.f;
        if (add_bias) { b0 = bias[col]; b1 = bias[col + 1]; }
#pragma unroll
        for (int mt = 0; mt < 4; mt++) {
            int row = m0 + wm * 64 + mt * 16 + g;
            float v00 = acc[mt][nt][0] + b0, v01 = acc[mt][nt][1] + b1;
            float v10 = acc[mt][nt][2] + b0, v11 = acc[mt][nt][3] + b1;
            if (round_out) {
                v00 = tf32r(v00); v01 = tf32r(v01);
                v10 = tf32r(v10); v11 = tf32r(v11);
            }
            *(float2*)(C + (long long)row * ldc + col) = make_float2(v00, v01);
            *(float2*)(C + (long long)(row + 8) * ldc + col) = make_float2(v10, v11);
        }
    }
}

// =====================================================================
// Fused attention, TF32 mma.sync (unchanged from R8)
// =====================================================================
#define ATT_SMEM_BYTES (56832 * 4)

__global__ __launch_bounds__(256) void attn_kernel(
    const float* __restrict__ Q, const float* __restrict__ Keys,
    const float* __restrict__ Vals, float* __restrict__ O)
{
    extern __shared__ float sm[];
    float* qs = sm;                     // [64][68]
    float* ks = qs + 64 * 68;           // [256][68]
    float* vs = ks + 256 * 68;          // [256][72]
    float* ps = vs + 256 * 72;          // [64][260]

    const int tid = threadIdx.x;
    const int wid = tid >> 5, lane = tid & 31;
    const int g   = lane >> 2, tig = lane & 3;
    const int wm  = wid >> 2;
    const int wn  = wid & 3;
    const int qt = blockIdx.x;
    const int h  = blockIdx.y;
    const int b  = blockIdx.z;

    const long long qbase  = ((long long)b * SEQN + qt * 64) * DIMN + h * DHN;
    const long long kvbase = ((long long)b * KLR) * DIMN + h * DHN;

#pragma unroll
    for (int i = 0; i < 4; i++) {
        int idx = tid + i * 256;
        int r = idx >> 4, c4 = (idx & 15) * 4;
        *(float4*)&qs[r * 68 + c4] =
            *(const float4*)(Q + qbase + (long long)r * DIMN + c4);
    }
#pragma unroll
    for (int i = 0; i < 16; i++) {
        int idx = tid + i * 256;
        int r = idx >> 4, c4 = (idx & 15) * 4;
        *(float4*)&ks[r * 68 + c4] =
            *(const float4*)(Keys + kvbase + (long long)r * DIMN + c4);
        *(float4*)&vs[r * 72 + c4] =
            *(const float4*)(Vals + kvbase + (long long)r * DIMN + c4);
    }
    __syncthreads();

    // S = Q·K^T
    {
        float sacc[2][8][4];
#pragma unroll
        for (int mt = 0; mt < 2; mt++)
#pragma unroll
            for (int nt = 0; nt < 8; nt++)
#pragma unroll
                for (int r = 0; r < 4; r++) sacc[mt][nt][r] = 0.f;

        const uint32_t* qsu = (const uint32_t*)qs;
        const uint32_t* ksu = (const uint32_t*)ks;
#pragma unroll
        for (int kk = 0; kk < 8; kk++) {
            int k = kk * 8;
            uint32_t af[2][4], bf[8][2];
#pragma unroll
            for (int mt = 0; mt < 2; mt++) {
                int row = wm * 32 + mt * 16 + g;
                af[mt][0] = qsu[row * 68 + k + tig];
                af[mt][1] = qsu[(row + 8) * 68 + k + tig];
                af[mt][2] = qsu[row * 68 + k + tig + 4];
                af[mt][3] = qsu[(row + 8) * 68 + k + tig + 4];
            }
#pragma unroll
            for (int nt = 0; nt < 8; nt++) {
                int nrow = wn * 64 + nt * 8 + g;
                bf[nt][0] = ksu[nrow * 68 + k + tig];
                bf[nt][1] = ksu[nrow * 68 + k + tig + 4];
            }
#pragma unroll
            for (int mt = 0; mt < 2; mt++)
#pragma unroll
                for (int nt = 0; nt < 8; nt++)
                    mma_tf32(sacc[mt][nt][0], sacc[mt][nt][1], sacc[mt][nt][2], sacc[mt][nt][3],
                             af[mt][0], af[mt][1], af[mt][2], af[mt][3],
                             bf[nt][0], bf[nt][1]);
        }
#pragma unroll
        for (int mt = 0; mt < 2; mt++) {
            int row = wm * 32 + mt * 16 + g;
#pragma unroll
            for (int nt = 0; nt < 8; nt++) {
                int col = wn * 64 + nt * 8 + tig * 2;
                ps[row * 260 + col]           = sacc[mt][nt][0] * 0.125f;
                ps[row * 260 + col + 1]       = sacc[mt][nt][1] * 0.125f;
                ps[(row + 8) * 260 + col]     = sacc[mt][nt][2] * 0.125f;
                ps[(row + 8) * 260 + col + 1] = sacc[mt][nt][3] * 0.125f;
            }
        }
    }
    __syncthreads();

    // softmax (fp32), store probs tf32-rounded
    {
        const int warp = wid;
        for (int rr = 0; rr < 8; rr++) {
            int r = warp * 8 + rr;
            float v[8], mx = -1e30f;
#pragma unroll
            for (int j = 0; j < 8; j++) {
                v[j] = ps[r * 260 + lane + j * 32];
                mx = fmaxf(mx, v[j]);
            }
#pragma unroll
            for (int s = 16; s > 0; s >>= 1)
                mx = fmaxf(mx, __shfl_xor_sync(0xffffffffu, mx, s));
            float sum = 0.f;
#pragma unroll
            for (int j = 0; j < 8; j++) { v[j] = __expf(v[j] - mx); sum += v[j]; }
#pragma unroll
            for (int s = 16; s > 0; s >>= 1)
                sum += __shfl_xor_sync(0xffffffffu, sum, s);
            float inv = 1.f / sum;
#pragma unroll
            for (int j = 0; j < 8; j++)
                ps[r * 260 + lane + j * 32] = tf32r(v[j] * inv);
        }
    }
    __syncthreads();

    // O = P·V
    {
        float oacc[2][2][4];
#pragma unroll
        for (int mt = 0; mt < 2; mt++)
#pragma unroll
            for (int nt = 0; nt < 2; nt++)
#pragma unroll
                for (int r = 0; r < 4; r++) oacc[mt][nt][r] = 0.f;

        const uint32_t* psu = (const uint32_t*)ps;
        const uint32_t* vsu = (const uint32_t*)vs;
#pragma unroll 4
        for (int kk = 0; kk < 32; kk++) {
            int k = kk * 8;
            uint32_t af[2][4], bf[2][2];
#pragma unroll
            for (int mt = 0; mt < 2; mt++) {
                int row = wm * 32 + mt * 16 + g;
                af[mt][0] = psu[row * 260 + k + tig];
                af[mt][1] = psu[(row + 8) * 260 + k + tig];
                af[mt][2] = psu[row * 260 + k + tig + 4];
                af[mt][3] = psu[(row + 8) * 260 + k + tig + 4];
            }
#pragma unroll
            for (int nt = 0; nt < 2; nt++) {
                int n = wn * 16 + nt * 8 + g;
                bf[nt][0] = vsu[(k + tig) * 72 + n];
                bf[nt][1] = vsu[(k + tig + 4) * 72 + n];
            }
#pragma unroll
            for (int mt = 0; mt < 2; mt++)
#pragma unroll
                for (int nt = 0; nt < 2; nt++)
                    mma_tf32(oacc[mt][nt][0], oacc[mt][nt][1], oacc[mt][nt][2], oacc[mt][nt][3],
                             af[mt][0], af[mt][1], af[mt][2], af[mt][3],
                             bf[nt][0], bf[nt][1]);
        }
#pragma unroll
        for (int mt = 0; mt < 2; mt++) {
            int row = wm * 32 + mt * 16 + g;
#pragma unroll
            for (int nt = 0; nt < 2; nt++) {
                int col = wn * 16 + nt * 8 + tig * 2;
                *(float2*)(O + qbase + (long long)row * DIMN + col) =
                    make_float2(tf32r(oacc[mt][nt][0]), tf32r(oacc[mt][nt][1]));
                *(float2*)(O + qbase + (long long)(row + 8) * DIMN + col) =
                    make_float2(tf32r(oacc[mt][nt][2]), tf32r(oacc[mt][nt][3]));
            }
        }
    }
}

// =====================================================================
// launch
// =====================================================================
extern "C" void kernel_launch(void* const* d_in, const int* in_sizes, int n_in,
                              void* d_out, int out_size)
{
    (void)in_sizes; (void)n_in; (void)out_size;

    const float* x  = (const float*)d_in[0];
    const float* Wq = (const float*)d_in[1];
    const float* Wk = (const float*)d_in[2];
    const float* Wv = (const float*)d_in[3];
    const float* pk = (const float*)d_in[4];
    const float* pv = (const float*)d_in[5];
    const float* Wo = (const float*)d_in[6];
    const float* bo = (const float*)d_in[7];
    float* out = (float*)d_out;

    float *Q, *AO, *keys, *vals, *xk, *xv;
    float *xt, *wqt, *wkt, *wvt, *wot, *pkt, *pvt;
    cudaGetSymbolAddress((void**)&Q, g_Q);
    cudaGetSymbolAddress((void**)&AO, g_AO);
    cudaGetSymbolAddress((void**)&keys, g_keys);
    cudaGetSymbolAddress((void**)&vals, g_vals);
    cudaGetSymbolAddress((void**)&xk, g_xk);
    cudaGetSymbolAddress((void**)&xv, g_xv);
    cudaGetSymbolAddress((void**)&xt, g_xt);
    cudaGetSymbolAddress((void**)&wqt, g_wqt);
    cudaGetSymbolAddress((void**)&wkt, g_wkt);
    cudaGetSymbolAddress((void**)&wvt, g_wvt);
    cudaGetSymbolAddress((void**)&wot, g_wot);
    cudaGetSymbolAddress((void**)&pkt, g_pkt);
    cudaGetSymbolAddress((void**)&pvt, g_pvt);

    // 0) round inputs to tf32 once
    {
        int n4x = (M_TOK * DIMN) / 4;
        round_tf32_kernel<<<(n4x + 255) / 256, 256>>>(x, xt, n4x);
        int n4w = (DIMN * DIMN) / 4;
        round_tf32_kernel<<<(n4w + 255) / 256, 256>>>(Wq, wqt, n4w);
        round_tf32_kernel<<<(n4w + 255) / 256, 256>>>(Wk, wkt, n4w);
        round_tf32_kernel<<<(n4w + 255) / 256, 256>>>(Wv, wvt, n4w);
        round_tf32_kernel<<<(n4w + 255) / 256, 256>>>(Wo, wot, n4w);
        int n4p = (SEQN * KLR) / 4;
        round_tf32_kernel<<<(n4p + 255) / 256, 256>>>(pk, pkt, n4p);
        round_tf32_kernel<<<(n4p + 255) / 256, 256>>>(pv, pvt, n4p);
    }

    cudaFuncSetAttribute(gemm_nt_big,
                         cudaFuncAttributeMaxDynamicSharedMemorySize,
                         NTBIG_SMEM);

    // 1) Q projection (big-tile NT) — output tf32-rounded (feeds attention)
    dim3 gbig(DIMN / 128, M_TOK / 256);
    gemm_nt_big<<<gbig, 256, NTBIG_SMEM>>>(xt, wqt, nullptr, Q,
                                           DIMN, DIMN, DIMN, DIMN, 0, 1);

    // 2) fused sequence projection: xk = pk^T x, xv = pv^T x (x staged once)
    dim3 gproj(DIMN / 128, KLR / 64, BATCHN);
    gemm_tn2_tf32<<<gproj, 256>>>(pkt, pvt, xt, xk, xv, SEQN, KLR, DIMN, DIMN,
                                  (long long)SEQN * DIMN, (long long)KLR * DIMN);

    // 3) keys = xk·Wk^T, vals = xv·Wv^T (outputs rounded, feed attention)
    dim3 gsmall(DIMN / 128, (BATCHN * KLR) / 128);
    gemm_nt_tf32<<<gsmall, 256>>>(xk, wkt, nullptr, keys, DIMN, DIMN, DIMN, DIMN, 0, 1);
    gemm_nt_tf32<<<gsmall, 256>>>(xv, wvt, nullptr, vals, DIMN, DIMN, DIMN, DIMN, 0, 1);

    // 4) fused attention (writes tf32-rounded AO)
    cudaFuncSetAttribute(attn_kernel,
                         cudaFuncAttributeMaxDynamicSharedMemorySize,
                         ATT_SMEM_BYTES);
    dim3 gatt(SEQN / 64, HEADSN, BATCHN);
    attn_kernel<<<gatt, 256, ATT_SMEM_BYTES>>>(Q, keys, vals, AO);

    // 5) output projection + bias (big-tile NT)
    gemm_nt_big<<<gbig, 256, NTBIG_SMEM>>>(AO, wot, bo, out,
                                           DIMN, DIMN, DIMN, DIMN, 1, 0);
}

// round 12
// speedup vs baseline: 1.2089x; 1.2089x over previous
#include <cuda_runtime.h>
#include <cstdint>

// ---------------- problem constants ----------------
#define M_TOK  16384     // BATCH * SEQ
#define DIMN   1024
#define KLR    256
#define BATCHN 4
#define SEQN   4096
#define HEADSN 16
#define DHN    64

// ---------------- scratch (device globals) ----------------
__device__ float g_Q[16384 * 1024];
__device__ float g_AO[16384 * 1024];
__device__ float g_keys[4 * 256 * 1024];
__device__ float g_vals[4 * 256 * 1024];
__device__ float g_xk[4 * 256 * 1024];
__device__ float g_xv[4 * 256 * 1024];
__device__ float g_xt[16384 * 1024];
__device__ float g_wqt[1024 * 1024];
__device__ float g_wkt[1024 * 1024];
__device__ float g_wvt[1024 * 1024];
__device__ float g_wot[1024 * 1024];
__device__ float g_pkt[4096 * 256];
__device__ float g_pvt[4096 * 256];

// ---------------- tf32 helpers ----------------
__device__ __forceinline__ float tf32r(float f) {
    uint32_t u;
    asm("cvt.rna.tf32.f32 %0, %1;" : "=r"(u) : "f"(f));
    return __uint_as_float(u);
}

__device__ __forceinline__ void mma_tf32(
    float& c0, float& c1, float& c2, float& c3,
    uint32_t a0, uint32_t a1, uint32_t a2, uint32_t a3,
    uint32_t b0, uint32_t b1)
{
    asm volatile(
        "mma.sync.aligned.m16n8k8.row.col.f32.tf32.tf32.f32 "
        "{%0,%1,%2,%3}, {%4,%5,%6,%7}, {%8,%9}, {%0,%1,%2,%3};\n"
        : "+f"(c0), "+f"(c1), "+f"(c2), "+f"(c3)
        : "r"(a0), "r"(a1), "r"(a2), "r"(a3), "r"(b0), "r"(b1));
}

// ldmatrix x4 over b16-view: four 8x8 b16 matrices == four 8x4 b32 tiles.
// Thread->fragment mapping matches m16n8k8 tf32 operands exactly.
#define LDSM_X4(r0, r1, r2, r3, addr) \
    asm volatile("ldmatrix.sync.aligned.m8n8.x4.shared.b16 {%0,%1,%2,%3}, [%4];" \
                 : "=r"(r0), "=r"(r1), "=r"(r2), "=r"(r3) : "r"(addr))

__device__ __forceinline__ void cp16(uint32_t smem, const void* g) {
    asm volatile("cp.async.cg.shared.global [%0], [%1], 16;\n"
                 :: "r"(smem), "l"(g));
}
__device__ __forceinline__ void cp_commit() {
    asm volatile("cp.async.commit_group;\n");
}
__device__ __forceinline__ void cp_wait0() {
    asm volatile("cp.async.wait_group 0;\n");
}
__device__ __forceinline__ uint32_t smem_u32(const void* p) {
    return (uint32_t)__cvta_generic_to_shared(p);
}

// ---------------- prep: round to tf32 (RNA) ----------------
__global__ __launch_bounds__(256) void round_tf32_kernel(
    const float* __restrict__ in, float* __restrict__ out, int n4)
{
    int i = blockIdx.x * 256 + threadIdx.x;
    if (i < n4) {
        float4 v = ((const float4*)in)[i];
        v.x = tf32r(v.x); v.y = tf32r(v.y); v.z = tf32r(v.z); v.w = tf32r(v.w);
        ((float4*)out)[i] = v;
    }
}

// =====================================================================
// NT TF32 GEMM: block 128x128, BK=16, 8 warps (2x4), warp tile 64x32.
// Fragment loads via ldmatrix.x4 (6 LDSM per k8-step vs 24 scalar LDS).
// smem rows stride 20 words -> conflict-free for both staging and LDSM.
// =====================================================================
__global__ __launch_bounds__(256, 2) void gemm_nt_tf32(
    const float* __restrict__ A, const float* __restrict__ B,
    const float* __restrict__ bias, float* __restrict__ C,
    int K, int lda, int ldb, int ldc, int add_bias, int round_out)
{
    __shared__ uint32_t As[2][128 * 20];
    __shared__ uint32_t Bs[2][128 * 20];

    const int tid  = threadIdx.x;
    const int wid  = tid >> 5, lane = tid & 31;
    const int g    = lane >> 2, tig = lane & 3;
    const int wm   = wid >> 2;            // 0..1 -> 64 rows
    const int wn   = wid & 3;             // 0..3 -> 32 cols
    const int m0   = blockIdx.y * 128;
    const int n0   = blockIdx.x * 128;

    const int lrow = tid >> 1;
    const int lkg  = (tid & 1) * 8;
    const float* Ag = A + (long long)(m0 + lrow) * lda + lkg;
    const float* Bg = B + (long long)(n0 + lrow) * ldb + lkg;

    const uint32_t sa0 = smem_u32(&As[0][lrow * 20 + lkg]);
    const uint32_t sa1 = smem_u32(&As[1][lrow * 20 + lkg]);
    const uint32_t sb0 = smem_u32(&Bs[0][lrow * 20 + lkg]);
    const uint32_t sb1 = smem_u32(&Bs[1][lrow * 20 + lkg]);

    // ldmatrix per-lane address offsets (bytes), stride 20 words = 80 B/row.
    // A x4: lanes 0-15 -> rows mr+lane cols 0-3; lanes 16-31 -> rows mr+(lane-16) cols 4-7.
    const uint32_t aLane = (uint32_t)(((lane & 15) * 20 + (lane >> 4) * 4) * 4);
    // B x4: {nt,cols0-3},{nt,cols4-7},{nt+1,cols0-3},{nt+1,cols4-7}
    const uint32_t bLane = (uint32_t)(((((lane >> 4) & 1) * 8 + (lane & 7)) * 20
                                      + ((lane >> 3) & 1) * 4) * 4);
    const uint32_t aF0 = smem_u32(As[0]) + (uint32_t)(wm * 64 * 80) + aLane;
    const uint32_t aF1 = smem_u32(As[1]) + (uint32_t)(wm * 64 * 80) + aLane;
    const uint32_t bF0 = smem_u32(Bs[0]) + (uint32_t)(wn * 32 * 80) + bLane;
    const uint32_t bF1 = smem_u32(Bs[1]) + (uint32_t)(wn * 32 * 80) + bLane;

    float acc[4][4][4];
#pragma unroll
    for (int mt = 0; mt < 4; mt++)
#pragma unroll
        for (int nt = 0; nt < 4; nt++)
#pragma unroll
            for (int r = 0; r < 4; r++) acc[mt][nt][r] = 0.f;

    cp16(sa0, Ag);      cp16(sa0 + 16, Ag + 4);
    cp16(sb0, Bg);      cp16(sb0 + 16, Bg + 4);
    cp_commit();

    int buf = 0;
    for (int k0 = 0; k0 < K; k0 += 16) {
        cp_wait0();
        __syncthreads();
        if (k0 + 16 < K) {
            uint32_t da = buf ? sa0 : sa1;
            uint32_t db = buf ? sb0 : sb1;
            cp16(da, Ag + k0 + 16);      cp16(da + 16, Ag + k0 + 20);
            cp16(db, Bg + k0 + 16);      cp16(db + 16, Bg + k0 + 20);
            cp_commit();
        }
        const uint32_t aF = buf ? aF1 : aF0;
        const uint32_t bF = buf ? bF1 : bF0;
#pragma unroll
        for (int ks = 0; ks < 2; ks++) {
            uint32_t af[4][4], bf[4][2];
#pragma unroll
            for (int mt = 0; mt < 4; mt++)
                LDSM_X4(af[mt][0], af[mt][1], af[mt][2], af[mt][3],
                        aF + (uint32_t)(mt * 16 * 80 + ks * 32));
#pragma unroll
            for (int np = 0; np < 2; np++)
                LDSM_X4(bf[2 * np][0], bf[2 * np][1], bf[2 * np + 1][0], bf[2 * np + 1][1],
                        bF + (uint32_t)(np * 16 * 80 + ks * 32));
#pragma unroll
            for (int mt = 0; mt < 4; mt++)
#pragma unroll
                for (int nt = 0; nt < 4; nt++)
                    mma_tf32(acc[mt][nt][0], acc[mt][nt][1], acc[mt][nt][2], acc[mt][nt][3],
                             af[mt][0], af[mt][1], af[mt][2], af[mt][3],
                             bf[nt][0], bf[nt][1]);
        }
        buf ^= 1;
    }

#pragma unroll
    for (int nt = 0; nt < 4; nt++) {
        int col = n0 + wn * 32 + nt * 8 + tig * 2;
        float b0 = 0.f, b1 = 0.f;
        if (add_bias) { b0 = bias[col]; b1 = bias[col + 1]; }
#pragma unroll
        for (int mt = 0; mt < 4; mt++) {
            int row = m0 + wm * 64 + mt * 16 + g;
            float v00 = acc[mt][nt][0] + b0, v01 = acc[mt][nt][1] + b1;
            float v10 = acc[mt][nt][2] + b0, v11 = acc[mt][nt][3] + b1;
            if (round_out) {
                v00 = tf32r(v00); v01 = tf32r(v01);
                v10 = tf32r(v10); v11 = tf32r(v11);
            }
            *(float2*)(C + (long long)row * ldc + col) = make_float2(v00, v01);
            *(float2*)(C + (long long)(row + 8) * ldc + col) = make_float2(v10, v11);
        }
    }
}

// =====================================================================
// FUSED TN TF32 GEMM (batched z): C1 = A1^T·B, C2 = A2^T·B (B staged once)
// =====================================================================
__global__ __launch_bounds__(256) void gemm_tn2_tf32(
    const float* __restrict__ A1, const float* __restrict__ A2,
    const float* __restrict__ B,
    float* __restrict__ C1, float* __restrict__ C2,
    int P, int lda, int ldb, int ldc, long long strideB, long long strideC)
{
    B  += (long long)blockIdx.z * strideB;
    C1 += (long long)blockIdx.z * strideC;
    C2 += (long long)blockIdx.z * strideC;

    __shared__ uint32_t As1[2][16 * 72];
    __shared__ uint32_t As2[2][16 * 72];
    __shared__ uint32_t Bs[2][16 * 136];

    const int tid  = threadIdx.x;
    const int wid  = tid >> 5, lane = tid & 31;
    const int g    = lane >> 2, tig = lane & 3;
    const int wm   = wid >> 2;
    const int wn   = wid & 3;
    const int m0   = blockIdx.y * 64;
    const int n0   = blockIdx.x * 128;

    const int lp   = tid >> 4;
    const int lma  = (tid & 15) * 4;
    const int lnb  = (tid & 15) * 8;
    const float* A1g = A1 + (long long)lp * lda + m0 + lma;
    const float* A2g = A2 + (long long)lp * lda + m0 + lma;
    const float* Bg  = B  + (long long)lp * ldb + n0 + lnb;

    uint32_t s1[2], s2[2], sbv[2];
#pragma unroll
    for (int b2 = 0; b2 < 2; b2++) {
        s1[b2]  = smem_u32(&As1[b2][lp * 72 + lma]);
        s2[b2]  = smem_u32(&As2[b2][lp * 72 + lma]);
        sbv[b2] = smem_u32(&Bs[b2][lp * 136 + lnb]);
    }

    float ac1[2][4][4], ac2[2][4][4];
#pragma unroll
    for (int mt = 0; mt < 2; mt++)
#pragma unroll
        for (int nt = 0; nt < 4; nt++)
#pragma unroll
            for (int r = 0; r < 4; r++) { ac1[mt][nt][r] = 0.f; ac2[mt][nt][r] = 0.f; }

    cp16(s1[0], A1g);
    cp16(s2[0], A2g);
    cp16(sbv[0], Bg);   cp16(sbv[0] + 16, Bg + 4);
    cp_commit();

    int buf = 0;
    for (int p0 = 0; p0 < P; p0 += 16) {
        cp_wait0();
        __syncthreads();
        if (p0 + 16 < P) {
            const int nb = buf ^ 1;
            const float* A1n = A1g + (long long)(p0 + 16) * lda;
            const float* A2n = A2g + (long long)(p0 + 16) * lda;
            const float* Bn  = Bg  + (long long)(p0 + 16) * ldb;
            cp16(s1[nb], A1n);
            cp16(s2[nb], A2n);
            cp16(sbv[nb], Bn);   cp16(sbv[nb] + 16, Bn + 4);
            cp_commit();
        }
        const uint32_t* Ab1 = As1[buf];
        const uint32_t* Ab2 = As2[buf];
        const uint32_t* Bb  = Bs[buf];
#pragma unroll
        for (int ks = 0; ks < 2; ks++) {
            uint32_t f1[2][4], f2[2][4], bf[4][2];
#pragma unroll
            for (int mt = 0; mt < 2; mt++) {
                int bm = wm * 32 + mt * 16 + g;
                f1[mt][0] = Ab1[(ks * 8 + tig) * 72 + bm];
                f1[mt][1] = Ab1[(ks * 8 + tig) * 72 + bm + 8];
                f1[mt][2] = Ab1[(ks * 8 + tig + 4) * 72 + bm];
                f1[mt][3] = Ab1[(ks * 8 + tig + 4) * 72 + bm + 8];
                f2[mt][0] = Ab2[(ks * 8 + tig) * 72 + bm];
                f2[mt][1] = Ab2[(ks * 8 + tig) * 72 + bm + 8];
                f2[mt][2] = Ab2[(ks * 8 + tig + 4) * 72 + bm];
                f2[mt][3] = Ab2[(ks * 8 + tig + 4) * 72 + bm + 8];
            }
#pragma unroll
            for (int nt = 0; nt < 4; nt++) {
                int bn = wn * 32 + nt * 8 + g;
                bf[nt][0] = Bb[(ks * 8 + tig) * 136 + bn];
                bf[nt][1] = Bb[(ks * 8 + tig + 4) * 136 + bn];
            }
#pragma unroll
            for (int mt = 0; mt < 2; mt++)
#pragma unroll
                for (int nt = 0; nt < 4; nt++) {
                    mma_tf32(ac1[mt][nt][0], ac1[mt][nt][1], ac1[mt][nt][2], ac1[mt][nt][3],
                             f1[mt][0], f1[mt][1], f1[mt][2], f1[mt][3],
                             bf[nt][0], bf[nt][1]);
                    mma_tf32(ac2[mt][nt][0], ac2[mt][nt][1], ac2[mt][nt][2], ac2[mt][nt][3],
                             f2[mt][0], f2[mt][1], f2[mt][2], f2[mt][3],
                             bf[nt][0], bf[nt][1]);
                }
        }
        buf ^= 1;
    }

#pragma unroll
    for (int mt = 0; mt < 2; mt++) {
        int row = m0 + wm * 32 + mt * 16 + g;
#pragma unroll
        for (int nt = 0; nt < 4; nt++) {
            int col = n0 + wn * 32 + nt * 8 + tig * 2;
            *(float2*)(C1 + (long long)row * ldc + col) =
                make_float2(tf32r(ac1[mt][nt][0]), tf32r(ac1[mt][nt][1]));
            *(float2*)(C1 + (long long)(row + 8) * ldc + col) =
                make_float2(tf32r(ac1[mt][nt][2]), tf32r(ac1[mt][nt][3]));
            *(float2*)(C2 + (long long)row * ldc + col) =
                make_float2(tf32r(ac2[mt][nt][0]), tf32r(ac2[mt][nt][1]));
            *(float2*)(C2 + (long long)(row + 8) * ldc + col) =
                make_float2(tf32r(ac2[mt][nt][2]), tf32r(ac2[mt][nt][3]));
        }
    }
}

// =====================================================================
// Fused attention, TF32 mma.sync (unchanged from R8)
// =====================================================================
#define ATT_SMEM_BYTES (56832 * 4)

__global__ __launch_bounds__(256) void attn_kernel(
    const float* __restrict__ Q, const float* __restrict__ Keys,
    const float* __restrict__ Vals, float* __restrict__ O)
{
    extern __shared__ float sm[];
    float* qs = sm;                     // [64][68]
    float* ks = qs + 64 * 68;           // [256][68]
    float* vs = ks + 256 * 68;          // [256][72]
    float* ps = vs + 256 * 72;          // [64][260]

    const int tid = threadIdx.x;
    const int wid = tid >> 5, lane = tid & 31;
    const int g   = lane >> 2, tig = lane & 3;
    const int wm  = wid >> 2;
    const int wn  = wid & 3;
    const int qt = blockIdx.x;
    const int h  = blockIdx.y;
    const int b  = blockIdx.z;

    const long long qbase  = ((long long)b * SEQN + qt * 64) * DIMN + h * DHN;
    const long long kvbase = ((long long)b * KLR) * DIMN + h * DHN;

#pragma unroll
    for (int i = 0; i < 4; i++) {
        int idx = tid + i * 256;
        int r = idx >> 4, c4 = (idx & 15) * 4;
        *(float4*)&qs[r * 68 + c4] =
            *(const float4*)(Q + qbase + (long long)r * DIMN + c4);
    }
#pragma unroll
    for (int i = 0; i < 16; i++) {
        int idx = tid + i * 256;
        int r = idx >> 4, c4 = (idx & 15) * 4;
        *(float4*)&ks[r * 68 + c4] =
            *(const float4*)(Keys + kvbase + (long long)r * DIMN + c4);
        *(float4*)&vs[r * 72 + c4] =
            *(const float4*)(Vals + kvbase + (long long)r * DIMN + c4);
    }
    __syncthreads();

    // S = Q·K^T
    {
        float sacc[2][8][4];
#pragma unroll
        for (int mt = 0; mt < 2; mt++)
#pragma unroll
            for (int nt = 0; nt < 8; nt++)
#pragma unroll
                for (int r = 0; r < 4; r++) sacc[mt][nt][r] = 0.f;

        const uint32_t* qsu = (const uint32_t*)qs;
        const uint32_t* ksu = (const uint32_t*)ks;
#pragma unroll
        for (int kk = 0; kk < 8; kk++) {
            int k = kk * 8;
            uint32_t af[2][4], bf[8][2];
#pragma unroll
            for (int mt = 0; mt < 2; mt++) {
                int row = wm * 32 + mt * 16 + g;
                af[mt][0] = qsu[row * 68 + k + tig];
                af[mt][1] = qsu[(row + 8) * 68 + k + tig];
                af[mt][2] = qsu[row * 68 + k + tig + 4];
                af[mt][3] = qsu[(row + 8) * 68 + k + tig + 4];
            }
#pragma unroll
            for (int nt = 0; nt < 8; nt++) {
                int nrow = wn * 64 + nt * 8 + g;
                bf[nt][0] = ksu[nrow * 68 + k + tig];
                bf[nt][1] = ksu[nrow * 68 + k + tig + 4];
            }
#pragma unroll
            for (int mt = 0; mt < 2; mt++)
#pragma unroll
                for (int nt = 0; nt < 8; nt++)
                    mma_tf32(sacc[mt][nt][0], sacc[mt][nt][1], sacc[mt][nt][2], sacc[mt][nt][3],
                             af[mt][0], af[mt][1], af[mt][2], af[mt][3],
                             bf[nt][0], bf[nt][1]);
        }
#pragma unroll
        for (int mt = 0; mt < 2; mt++) {
            int row = wm * 32 + mt * 16 + g;
#pragma unroll
            for (int nt = 0; nt < 8; nt++) {
                int col = wn * 64 + nt * 8 + tig * 2;
                ps[row * 260 + col]           = sacc[mt][nt][0] * 0.125f;
                ps[row * 260 + col + 1]       = sacc[mt][nt][1] * 0.125f;
                ps[(row + 8) * 260 + col]     = sacc[mt][nt][2] * 0.125f;
                ps[(row + 8) * 260 + col + 1] = sacc[mt][nt][3] * 0.125f;
            }
        }
    }
    __syncthreads();

    // softmax (fp32), store probs tf32-rounded
    {
        const int warp = wid;
        for (int rr = 0; rr < 8; rr++) {
            int r = warp * 8 + rr;
            float v[8], mx = -1e30f;
#pragma unroll
            for (int j = 0; j < 8; j++) {
                v[j] = ps[r * 260 + lane + j * 32];
                mx = fmaxf(mx, v[j]);
            }
#pragma unroll
            for (int s = 16; s > 0; s >>= 1)
                mx = fmaxf(mx, __shfl_xor_sync(0xffffffffu, mx, s));
            float sum = 0.f;
#pragma unroll
            for (int j = 0; j < 8; j++) { v[j] = __expf(v[j] - mx); sum += v[j]; }
#pragma unroll
            for (int s = 16; s > 0; s >>= 1)
                sum += __shfl_xor_sync(0xffffffffu, sum, s);
            float inv = 1.f / sum;
#pragma unroll
            for (int j = 0; j < 8; j++)
                ps[r * 260 + lane + j * 32] = tf32r(v[j] * inv);
        }
    }
    __syncthreads();

    // O = P·V
    {
        float oacc[2][2][4];
#pragma unroll
        for (int mt = 0; mt < 2; mt++)
#pragma unroll
            for (int nt = 0; nt < 2; nt++)
#pragma unroll
                for (int r = 0; r < 4; r++) oacc[mt][nt][r] = 0.f;

        const uint32_t* psu = (const uint32_t*)ps;
        const uint32_t* vsu = (const uint32_t*)vs;
#pragma unroll 4
        for (int kk = 0; kk < 32; kk++) {
            int k = kk * 8;
            uint32_t af[2][4], bf[2][2];
#pragma unroll
            for (int mt = 0; mt < 2; mt++) {
                int row = wm * 32 + mt * 16 + g;
                af[mt][0] = psu[row * 260 + k + tig];
                af[mt][1] = psu[(row + 8) * 260 + k + tig];
                af[mt][2] = psu[row * 260 + k + tig + 4];
                af[mt][3] = psu[(row + 8) * 260 + k + tig + 4];
            }
#pragma unroll
            for (int nt = 0; nt < 2; nt++) {
                int n = wn * 16 + nt * 8 + g;
                bf[nt][0] = vsu[(k + tig) * 72 + n];
                bf[nt][1] = vsu[(k + tig + 4) * 72 + n];
            }
#pragma unroll
            for (int mt = 0; mt < 2; mt++)
#pragma unroll
                for (int nt = 0; nt < 2; nt++)
                    mma_tf32(oacc[mt][nt][0], oacc[mt][nt][1], oacc[mt][nt][2], oacc[mt][nt][3],
                             af[mt][0], af[mt][1], af[mt][2], af[mt][3],
                             bf[nt][0], bf[nt][1]);
        }
#pragma unroll
        for (int mt = 0; mt < 2; mt++) {
            int row = wm * 32 + mt * 16 + g;
#pragma unroll
            for (int nt = 0; nt < 2; nt++) {
                int col = wn * 16 + nt * 8 + tig * 2;
                *(float2*)(O + qbase + (long long)row * DIMN + col) =
                    make_float2(tf32r(oacc[mt][nt][0]), tf32r(oacc[mt][nt][1]));
                *(float2*)(O + qbase + (long long)(row + 8) * DIMN + col) =
                    make_float2(tf32r(oacc[mt][nt][2]), tf32r(oacc[mt][nt][3]));
            }
        }
    }
}

// =====================================================================
// launch
// =====================================================================
extern "C" void kernel_launch(void* const* d_in, const int* in_sizes, int n_in,
                              void* d_out, int out_size)
{
    (void)in_sizes; (void)n_in; (void)out_size;

    const float* x  = (const float*)d_in[0];
    const float* Wq = (const float*)d_in[1];
    const float* Wk = (const float*)d_in[2];
    const float* Wv = (const float*)d_in[3];
    const float* pk = (const float*)d_in[4];
    const float* pv = (const float*)d_in[5];
    const float* Wo = (const float*)d_in[6];
    const float* bo = (const float*)d_in[7];
    float* out = (float*)d_out;

    float *Q, *AO, *keys, *vals, *xk, *xv;
    float *xt, *wqt, *wkt, *wvt, *wot, *pkt, *pvt;
    cudaGetSymbolAddress((void**)&Q, g_Q);
    cudaGetSymbolAddress((void**)&AO, g_AO);
    cudaGetSymbolAddress((void**)&keys, g_keys);
    cudaGetSymbolAddress((void**)&vals, g_vals);
    cudaGetSymbolAddress((void**)&xk, g_xk);
    cudaGetSymbolAddress((void**)&xv, g_xv);
    cudaGetSymbolAddress((void**)&xt, g_xt);
    cudaGetSymbolAddress((void**)&wqt, g_wqt);
    cudaGetSymbolAddress((void**)&wkt, g_wkt);
    cudaGetSymbolAddress((void**)&wvt, g_wvt);
    cudaGetSymbolAddress((void**)&wot, g_wot);
    cudaGetSymbolAddress((void**)&pkt, g_pkt);
    cudaGetSymbolAddress((void**)&pvt, g_pvt);

    // 0) round inputs to tf32 once
    {
        int n4x = (M_TOK * DIMN) / 4;
        round_tf32_kernel<<<(n4x + 255) / 256, 256>>>(x, xt, n4x);
        int n4w = (DIMN * DIMN) / 4;
        round_tf32_kernel<<<(n4w + 255) / 256, 256>>>(Wq, wqt, n4w);
        round_tf32_kernel<<<(n4w + 255) / 256, 256>>>(Wk, wkt, n4w);
        round_tf32_kernel<<<(n4w + 255) / 256, 256>>>(Wv, wvt, n4w);
        round_tf32_kernel<<<(n4w + 255) / 256, 256>>>(Wo, wot, n4w);
        int n4p = (SEQN * KLR) / 4;
        round_tf32_kernel<<<(n4p + 255) / 256, 256>>>(pk, pkt, n4p);
        round_tf32_kernel<<<(n4p + 255) / 256, 256>>>(pv, pvt, n4p);
    }

    // 1) Q projection (ldmatrix NT) — output tf32-rounded (feeds attention)
    dim3 gbig(DIMN / 128, M_TOK / 128);
    gemm_nt_tf32<<<gbig, 256>>>(xt, wqt, nullptr, Q, DIMN, DIMN, DIMN, DIMN, 0, 1);

    // 2) fused sequence projection: xk = pk^T x, xv = pv^T x (x staged once)
    dim3 gproj(DIMN / 128, KLR / 64, BATCHN);
    gemm_tn2_tf32<<<gproj, 256>>>(pkt, pvt, xt, xk, xv, SEQN, KLR, DIMN, DIMN,
                                  (long long)SEQN * DIMN, (long long)KLR * DIMN);

    // 3) keys = xk·Wk^T, vals = xv·Wv^T (outputs rounded, feed attention)
    dim3 gsmall(DIMN / 128, (BATCHN * KLR) / 128);
    gemm_nt_tf32<<<gsmall, 256>>>(xk, wkt, nullptr, keys, DIMN, DIMN, DIMN, DIMN, 0, 1);
    gemm_nt_tf32<<<gsmall, 256>>>(xv, wvt, nullptr, vals, DIMN, DIMN, DIMN, DIMN, 0, 1);

    // 4) fused attention (writes tf32-rounded AO)
    cudaFuncSetAttribute(attn_kernel,
                         cudaFuncAttributeMaxDynamicSharedMemorySize,
                         ATT_SMEM_BYTES);
    dim3 gatt(SEQN / 64, HEADSN, BATCHN);
    attn_kernel<<<gatt, 256, ATT_SMEM_BYTES>>>(Q, keys, vals, AO);

    // 5) output projection + bias (ldmatrix NT)
    gemm_nt_tf32<<<gbig, 256>>>(AO, wot, bo, out, DIMN, DIMN, DIMN, DIMN, 1, 0);
}

// round 13
// speedup vs baseline: 1.3093x; 1.0830x over previous
#include <cuda_runtime.h>
#include <cstdint>

// ---------------- problem constants ----------------
#define M_TOK  16384     // BATCH * SEQ
#define DIMN   1024
#define KLR    256
#define BATCHN 4
#define SEQN   4096
#define HEADSN 16
#define DHN    64

// ---------------- scratch (device globals) ----------------
__device__ float g_Q[16384 * 1024];
__device__ float g_AO[16384 * 1024];
__device__ float g_keys[4 * 256 * 1024];
__device__ float g_vals[4 * 256 * 1024];
__device__ float g_xk[4 * 256 * 1024];
__device__ float g_xv[4 * 256 * 1024];
__device__ float g_xt[16384 * 1024];
__device__ float g_wqt[1024 * 1024];
__device__ float g_wkt[1024 * 1024];
__device__ float g_wvt[1024 * 1024];
__device__ float g_wot[1024 * 1024];
__device__ float g_pkt[4096 * 256];
__device__ float g_pvt[4096 * 256];

// ---------------- tf32 helpers ----------------
__device__ __forceinline__ float tf32r(float f) {
    uint32_t u;
    asm("cvt.rna.tf32.f32 %0, %1;" : "=r"(u) : "f"(f));
    return __uint_as_float(u);
}

__device__ __forceinline__ void mma_tf32(
    float& c0, float& c1, float& c2, float& c3,
    uint32_t a0, uint32_t a1, uint32_t a2, uint32_t a3,
    uint32_t b0, uint32_t b1)
{
    asm volatile(
        "mma.sync.aligned.m16n8k8.row.col.f32.tf32.tf32.f32 "
        "{%0,%1,%2,%3}, {%4,%5,%6,%7}, {%8,%9}, {%0,%1,%2,%3};\n"
        : "+f"(c0), "+f"(c1), "+f"(c2), "+f"(c3)
        : "r"(a0), "r"(a1), "r"(a2), "r"(a3), "r"(b0), "r"(b1));
}

#define LDSM_X4(r0, r1, r2, r3, addr) \
    asm volatile("ldmatrix.sync.aligned.m8n8.x4.shared.b16 {%0,%1,%2,%3}, [%4];" \
                 : "=r"(r0), "=r"(r1), "=r"(r2), "=r"(r3) : "r"(addr))

__device__ __forceinline__ void cp16(uint32_t smem, const void* g) {
    asm volatile("cp.async.cg.shared.global [%0], [%1], 16;\n"
                 :: "r"(smem), "l"(g));
}
__device__ __forceinline__ void cp_commit() {
    asm volatile("cp.async.commit_group;\n");
}
__device__ __forceinline__ void cp_wait0() {
    asm volatile("cp.async.wait_group 0;\n");
}
__device__ __forceinline__ void cp_wait2() {
    asm volatile("cp.async.wait_group 2;\n");
}
__device__ __forceinline__ uint32_t smem_u32(const void* p) {
    return (uint32_t)__cvta_generic_to_shared(p);
}

// ---------------- prep: round to tf32 (RNA) ----------------
__global__ __launch_bounds__(256) void round_tf32_kernel(
    const float* __restrict__ in, float* __restrict__ out, int n4)
{
    int i = blockIdx.x * 256 + threadIdx.x;
    if (i < n4) {
        float4 v = ((const float4*)in)[i];
        v.x = tf32r(v.x); v.y = tf32r(v.y); v.z = tf32r(v.z); v.w = tf32r(v.w);
        ((float4*)out)[i] = v;
    }
}

// =====================================================================
// NT TF32 GEMM: block 128x128, BK=16, 8 warps, warp tile 64x32.
// ldmatrix fragment loads + 4-stage cp.async pipeline (wait_group 2).
// Dynamic smem: 4 stages x (A 2560 + B 2560) words = 81920 B.
// =====================================================================
#define NT_SMEM (8 * 2560 * 4)
#define NT_STAGE_BYTES (2560 * 4)     // 10240 B per matrix per stage

__global__ __launch_bounds__(256, 2) void gemm_nt_tf32(
    const float* __restrict__ A, const float* __restrict__ B,
    const float* __restrict__ bias, float* __restrict__ C,
    int K, int lda, int ldb, int ldc, int add_bias, int round_out)
{
    extern __shared__ uint32_t dsm[];
    const uint32_t ab = smem_u32(dsm);                 // A stages base
    const uint32_t bb = ab + 4 * NT_STAGE_BYTES;       // B stages base

    const int tid  = threadIdx.x;
    const int wid  = tid >> 5, lane = tid & 31;
    const int g    = lane >> 2, tig = lane & 3;
    const int wm   = wid >> 2;            // 0..1 -> 64 rows
    const int wn   = wid & 3;             // 0..3 -> 32 cols
    const int m0   = blockIdx.y * 128;
    const int n0   = blockIdx.x * 128;

    const int lrow = tid >> 1;
    const int lkg  = (tid & 1) * 8;
    const float* Ag = A + (long long)(m0 + lrow) * lda + lkg;
    const float* Bg = B + (long long)(n0 + lrow) * ldb + lkg;

    const uint32_t stOff = (uint32_t)((lrow * 20 + lkg) * 4);

    // ldmatrix per-lane offsets (bytes), row stride 20 words = 80 B
    const uint32_t aLane = (uint32_t)(((lane & 15) * 20 + (lane >> 4) * 4) * 4);
    const uint32_t bLane = (uint32_t)(((((lane >> 4) & 1) * 8 + (lane & 7)) * 20
                                      + ((lane >> 3) & 1) * 4) * 4);
    const uint32_t aFrag = ab + (uint32_t)(wm * 64 * 80) + aLane;
    const uint32_t bFrag = bb + (uint32_t)(wn * 32 * 80) + bLane;

    float acc[4][4][4];
#pragma unroll
    for (int mt = 0; mt < 4; mt++)
#pragma unroll
        for (int nt = 0; nt < 4; nt++)
#pragma unroll
            for (int r = 0; r < 4; r++) acc[mt][nt][r] = 0.f;

    const int ntiles = K >> 4;
    // prologue: stage tiles 0,1,2
#pragma unroll
    for (int t = 0; t < 3; t++) {
        if (t < ntiles) {
            const uint32_t so = (uint32_t)(t & 3) * NT_STAGE_BYTES;
            const float* Ap = Ag + t * 16;
            const float* Bp = Bg + t * 16;
            cp16(ab + so + stOff, Ap);      cp16(ab + so + stOff + 16, Ap + 4);
            cp16(bb + so + stOff, Bp);      cp16(bb + so + stOff + 16, Bp + 4);
        }
        cp_commit();
    }

    for (int i = 0; i < ntiles; i++) {
        cp_wait2();                        // tile i's group retired
        __syncthreads();
        {
            const int t = i + 3;
            if (t < ntiles) {
                const uint32_t so = (uint32_t)(t & 3) * NT_STAGE_BYTES;
                const float* Ap = Ag + t * 16;
                const float* Bp = Bg + t * 16;
                cp16(ab + so + stOff, Ap);  cp16(ab + so + stOff + 16, Ap + 4);
                cp16(bb + so + stOff, Bp);  cp16(bb + so + stOff + 16, Bp + 4);
            }
            cp_commit();                   // empty group in the tail keeps count uniform
        }
        const uint32_t so = (uint32_t)(i & 3) * NT_STAGE_BYTES;
        const uint32_t aF = aFrag + so;
        const uint32_t bF = bFrag + so;
#pragma unroll
        for (int ks = 0; ks < 2; ks++) {
            uint32_t af[4][4], bf[4][2];
#pragma unroll
            for (int mt = 0; mt < 4; mt++)
                LDSM_X4(af[mt][0], af[mt][1], af[mt][2], af[mt][3],
                        aF + (uint32_t)(mt * 16 * 80 + ks * 32));
#pragma unroll
            for (int np = 0; np < 2; np++)
                LDSM_X4(bf[2 * np][0], bf[2 * np][1], bf[2 * np + 1][0], bf[2 * np + 1][1],
                        bF + (uint32_t)(np * 16 * 80 + ks * 32));
#pragma unroll
            for (int mt = 0; mt < 4; mt++)
#pragma unroll
                for (int nt = 0; nt < 4; nt++)
                    mma_tf32(acc[mt][nt][0], acc[mt][nt][1], acc[mt][nt][2], acc[mt][nt][3],
                             af[mt][0], af[mt][1], af[mt][2], af[mt][3],
                             bf[nt][0], bf[nt][1]);
        }
    }
    cp_wait0();

#pragma unroll
    for (int nt = 0; nt < 4; nt++) {
        int col = n0 + wn * 32 + nt * 8 + tig * 2;
        float b0 = 0.f, b1 = 0.f;
        if (add_bias) { b0 = bias[col]; b1 = bias[col + 1]; }
#pragma unroll
        for (int mt = 0; mt < 4; mt++) {
            int row = m0 + wm * 64 + mt * 16 + g;
            float v00 = acc[mt][nt][0] + b0, v01 = acc[mt][nt][1] + b1;
            float v10 = acc[mt][nt][2] + b0, v11 = acc[mt][nt][3] + b1;
            if (round_out) {
                v00 = tf32r(v00); v01 = tf32r(v01);
                v10 = tf32r(v10); v11 = tf32r(v11);
            }
            *(float2*)(C + (long long)row * ldc + col) = make_float2(v00, v01);
            *(float2*)(C + (long long)(row + 8) * ldc + col) = make_float2(v10, v11);
        }
    }
}

// =====================================================================
// FUSED TN TF32 GEMM (batched z): C1 = A1^T·B, C2 = A2^T·B (B staged once)
// =====================================================================
__global__ __launch_bounds__(256) void gemm_tn2_tf32(
    const float* __restrict__ A1, const float* __restrict__ A2,
    const float* __restrict__ B,
    float* __restrict__ C1, float* __restrict__ C2,
    int P, int lda, int ldb, int ldc, long long strideB, long long strideC)
{
    B  += (long long)blockIdx.z * strideB;
    C1 += (long long)blockIdx.z * strideC;
    C2 += (long long)blockIdx.z * strideC;

    __shared__ uint32_t As1[2][16 * 72];
    __shared__ uint32_t As2[2][16 * 72];
    __shared__ uint32_t Bs[2][16 * 136];

    const int tid  = threadIdx.x;
    const int wid  = tid >> 5, lane = tid & 31;
    const int g    = lane >> 2, tig = lane & 3;
    const int wm   = wid >> 2;
    const int wn   = wid & 3;
    const int m0   = blockIdx.y * 64;
    const int n0   = blockIdx.x * 128;

    const int lp   = tid >> 4;
    const int lma  = (tid & 15) * 4;
    const int lnb  = (tid & 15) * 8;
    const float* A1g = A1 + (long long)lp * lda + m0 + lma;
    const float* A2g = A2 + (long long)lp * lda + m0 + lma;
    const float* Bg  = B  + (long long)lp * ldb + n0 + lnb;

    uint32_t s1[2], s2[2], sbv[2];
#pragma unroll
    for (int b2 = 0; b2 < 2; b2++) {
        s1[b2]  = smem_u32(&As1[b2][lp * 72 + lma]);
        s2[b2]  = smem_u32(&As2[b2][lp * 72 + lma]);
        sbv[b2] = smem_u32(&Bs[b2][lp * 136 + lnb]);
    }

    float ac1[2][4][4], ac2[2][4][4];
#pragma unroll
    for (int mt = 0; mt < 2; mt++)
#pragma unroll
        for (int nt = 0; nt < 4; nt++)
#pragma unroll
            for (int r = 0; r < 4; r++) { ac1[mt][nt][r] = 0.f; ac2[mt][nt][r] = 0.f; }

    cp16(s1[0], A1g);
    cp16(s2[0], A2g);
    cp16(sbv[0], Bg);   cp16(sbv[0] + 16, Bg + 4);
    cp_commit();

    int buf = 0;
    for (int p0 = 0; p0 < P; p0 += 16) {
        cp_wait0();
        __syncthreads();
        if (p0 + 16 < P) {
            const int nb = buf ^ 1;
            const float* A1n = A1g + (long long)(p0 + 16) * lda;
            const float* A2n = A2g + (long long)(p0 + 16) * lda;
            const float* Bn  = Bg  + (long long)(p0 + 16) * ldb;
            cp16(s1[nb], A1n);
            cp16(s2[nb], A2n);
            cp16(sbv[nb], Bn);   cp16(sbv[nb] + 16, Bn + 4);
            cp_commit();
        }
        const uint32_t* Ab1 = As1[buf];
        const uint32_t* Ab2 = As2[buf];
        const uint32_t* Bb  = Bs[buf];
#pragma unroll
        for (int ks = 0; ks < 2; ks++) {
            uint32_t f1[2][4], f2[2][4], bf[4][2];
#pragma unroll
            for (int mt = 0; mt < 2; mt++) {
                int bm = wm * 32 + mt * 16 + g;
                f1[mt][0] = Ab1[(ks * 8 + tig) * 72 + bm];
                f1[mt][1] = Ab1[(ks * 8 + tig) * 72 + bm + 8];
                f1[mt][2] = Ab1[(ks * 8 + tig + 4) * 72 + bm];
                f1[mt][3] = Ab1[(ks * 8 + tig + 4) * 72 + bm + 8];
                f2[mt][0] = Ab2[(ks * 8 + tig) * 72 + bm];
                f2[mt][1] = Ab2[(ks * 8 + tig) * 72 + bm + 8];
                f2[mt][2] = Ab2[(ks * 8 + tig + 4) * 72 + bm];
                f2[mt][3] = Ab2[(ks * 8 + tig + 4) * 72 + bm + 8];
            }
#pragma unroll
            for (int nt = 0; nt < 4; nt++) {
                int bn = wn * 32 + nt * 8 + g;
                bf[nt][0] = Bb[(ks * 8 + tig) * 136 + bn];
                bf[nt][1] = Bb[(ks * 8 + tig + 4) * 136 + bn];
            }
#pragma unroll
            for (int mt = 0; mt < 2; mt++)
#pragma unroll
                for (int nt = 0; nt < 4; nt++) {
                    mma_tf32(ac1[mt][nt][0], ac1[mt][nt][1], ac1[mt][nt][2], ac1[mt][nt][3],
                             f1[mt][0], f1[mt][1], f1[mt][2], f1[mt][3],
                             bf[nt][0], bf[nt][1]);
                    mma_tf32(ac2[mt][nt][0], ac2[mt][nt][1], ac2[mt][nt][2], ac2[mt][nt][3],
                             f2[mt][0], f2[mt][1], f2[mt][2], f2[mt][3],
                             bf[nt][0], bf[nt][1]);
                }
        }
        buf ^= 1;
    }

#pragma unroll
    for (int mt = 0; mt < 2; mt++) {
        int row = m0 + wm * 32 + mt * 16 + g;
#pragma unroll
        for (int nt = 0; nt < 4; nt++) {
            int col = n0 + wn * 32 + nt * 8 + tig * 2;
            *(float2*)(C1 + (long long)row * ldc + col) =
                make_float2(tf32r(ac1[mt][nt][0]), tf32r(ac1[mt][nt][1]));
            *(float2*)(C1 + (long long)(row + 8) * ldc + col) =
                make_float2(tf32r(ac1[mt][nt][2]), tf32r(ac1[mt][nt][3]));
            *(float2*)(C2 + (long long)row * ldc + col) =
                make_float2(tf32r(ac2[mt][nt][0]), tf32r(ac2[mt][nt][1]));
            *(float2*)(C2 + (long long)(row + 8) * ldc + col) =
                make_float2(tf32r(ac2[mt][nt][2]), tf32r(ac2[mt][nt][3]));
        }
    }
}

// =====================================================================
// Fused attention, TF32 mma.sync; ldmatrix for S-phase A/B and PV A.
// =====================================================================
#define ATT_SMEM_BYTES (56832 * 4)

__global__ __launch_bounds__(256) void attn_kernel(
    const float* __restrict__ Q, const float* __restrict__ Keys,
    const float* __restrict__ Vals, float* __restrict__ O)
{
    extern __shared__ float sm[];
    float* qs = sm;                     // [64][68]
    float* ks = qs + 64 * 68;           // [256][68]
    float* vs = ks + 256 * 68;          // [256][72]
    float* ps = vs + 256 * 72;          // [64][260]

    const int tid = threadIdx.x;
    const int wid = tid >> 5, lane = tid & 31;
    const int g   = lane >> 2, tig = lane & 3;
    const int wm  = wid >> 2;
    const int wn  = wid & 3;
    const int qt = blockIdx.x;
    const int h  = blockIdx.y;
    const int b  = blockIdx.z;

    const long long qbase  = ((long long)b * SEQN + qt * 64) * DIMN + h * DHN;
    const long long kvbase = ((long long)b * KLR) * DIMN + h * DHN;

#pragma unroll
    for (int i = 0; i < 4; i++) {
        int idx = tid + i * 256;
        int r = idx >> 4, c4 = (idx & 15) * 4;
        *(float4*)&qs[r * 68 + c4] =
            *(const float4*)(Q + qbase + (long long)r * DIMN + c4);
    }
#pragma unroll
    for (int i = 0; i < 16; i++) {
        int idx = tid + i * 256;
        int r = idx >> 4, c4 = (idx & 15) * 4;
        *(float4*)&ks[r * 68 + c4] =
            *(const float4*)(Keys + kvbase + (long long)r * DIMN + c4);
        *(float4*)&vs[r * 72 + c4] =
            *(const float4*)(Vals + kvbase + (long long)r * DIMN + c4);
    }
    __syncthreads();

    // ldmatrix lane offsets (bytes)
    const uint32_t aL68 = (uint32_t)(((lane & 15) * 68 + (lane >> 4) * 4) * 4);
    const uint32_t bL68 = (uint32_t)(((((lane >> 4) & 1) * 8 + (lane & 7)) * 68
                                     + ((lane >> 3) & 1) * 4) * 4);
    const uint32_t aL260 = (uint32_t)(((lane & 15) * 260 + (lane >> 4) * 4) * 4);

    // S = Q·K^T
    {
        float sacc[2][8][4];
#pragma unroll
        for (int mt = 0; mt < 2; mt++)
#pragma unroll
            for (int nt = 0; nt < 8; nt++)
#pragma unroll
                for (int r = 0; r < 4; r++) sacc[mt][nt][r] = 0.f;

        const uint32_t qB = smem_u32(qs) + (uint32_t)(wm * 32 * 68 * 4) + aL68;
        const uint32_t kB = smem_u32(ks) + (uint32_t)(wn * 64 * 68 * 4) + bL68;
#pragma unroll
        for (int kk = 0; kk < 8; kk++) {
            const uint32_t ko = (uint32_t)(kk * 8 * 4);
            uint32_t af[2][4], bf[8][2];
#pragma unroll
            for (int mt = 0; mt < 2; mt++)
                LDSM_X4(af[mt][0], af[mt][1], af[mt][2], af[mt][3],
                        qB + (uint32_t)(mt * 16 * 68 * 4) + ko);
#pragma unroll
            for (int np = 0; np < 4; np++)
                LDSM_X4(bf[2 * np][0], bf[2 * np][1], bf[2 * np + 1][0], bf[2 * np + 1][1],
                        kB + (uint32_t)(np * 16 * 68 * 4) + ko);
#pragma unroll
            for (int mt = 0; mt < 2; mt++)
#pragma unroll
                for (int nt = 0; nt < 8; nt++)
                    mma_tf32(sacc[mt][nt][0], sacc[mt][nt][1], sacc[mt][nt][2], sacc[mt][nt][3],
                             af[mt][0], af[mt][1], af[mt][2], af[mt][3],
                             bf[nt][0], bf[nt][1]);
        }
#pragma unroll
        for (int mt = 0; mt < 2; mt++) {
            int row = wm * 32 + mt * 16 + g;
#pragma unroll
            for (int nt = 0; nt < 8; nt++) {
                int col = wn * 64 + nt * 8 + tig * 2;
                ps[row * 260 + col]           = sacc[mt][nt][0] * 0.125f;
                ps[row * 260 + col + 1]       = sacc[mt][nt][1] * 0.125f;
                ps[(row + 8) * 260 + col]     = sacc[mt][nt][2] * 0.125f;
                ps[(row + 8) * 260 + col + 1] = sacc[mt][nt][3] * 0.125f;
            }
        }
    }
    __syncthreads();

    // softmax (fp32), store probs tf32-rounded
    {
        const int warp = wid;
        for (int rr = 0; rr < 8; rr++) {
            int r = warp * 8 + rr;
            float v[8], mx = -1e30f;
#pragma unroll
            for (int j = 0; j < 8; j++) {
                v[j] = ps[r * 260 + lane + j * 32];
                mx = fmaxf(mx, v[j]);
            }
#pragma unroll
            for (int s = 16; s > 0; s >>= 1)
                mx = fmaxf(mx, __shfl_xor_sync(0xffffffffu, mx, s));
            float sum = 0.f;
#pragma unroll
            for (int j = 0; j < 8; j++) { v[j] = __expf(v[j] - mx); sum += v[j]; }
#pragma unroll
            for (int s = 16; s > 0; s >>= 1)
                sum += __shfl_xor_sync(0xffffffffu, sum, s);
            float inv = 1.f / sum;
#pragma unroll
            for (int j = 0; j < 8; j++)
                ps[r * 260 + lane + j * 32] = tf32r(v[j] * inv);
        }
    }
    __syncthreads();

    // O = P·V
    {
        float oacc[2][2][4];
#pragma unroll
        for (int mt = 0; mt < 2; mt++)
#pragma unroll
            for (int nt = 0; nt < 2; nt++)
#pragma unroll
                for (int r = 0; r < 4; r++) oacc[mt][nt][r] = 0.f;

        const uint32_t pB = smem_u32(ps) + (uint32_t)(wm * 32 * 260 * 4) + aL260;
        const uint32_t* vsu = (const uint32_t*)vs;
#pragma unroll 4
        for (int kk = 0; kk < 32; kk++) {
            int k = kk * 8;
            uint32_t af[2][4], bf[2][2];
#pragma unroll
            for (int mt = 0; mt < 2; mt++)
                LDSM_X4(af[mt][0], af[mt][1], af[mt][2], af[mt][3],
                        pB + (uint32_t)(mt * 16 * 260 * 4 + k * 4));
#pragma unroll
            for (int nt = 0; nt < 2; nt++) {
                int n = wn * 16 + nt * 8 + g;
                bf[nt][0] = vsu[(k + tig) * 72 + n];
                bf[nt][1] = vsu[(k + tig + 4) * 72 + n];
            }
#pragma unroll
            for (int mt = 0; mt < 2; mt++)
#pragma unroll
                for (int nt = 0; nt < 2; nt++)
                    mma_tf32(oacc[mt][nt][0], oacc[mt][nt][1], oacc[mt][nt][2], oacc[mt][nt][3],
                             af[mt][0], af[mt][1], af[mt][2], af[mt][3],
                             bf[nt][0], bf[nt][1]);
        }
#pragma unroll
        for (int mt = 0; mt < 2; mt++) {
            int row = wm * 32 + mt * 16 + g;
#pragma unroll
            for (int nt = 0; nt < 2; nt++) {
                int col = wn * 16 + nt * 8 + tig * 2;
                *(float2*)(O + qbase + (long long)row * DIMN + col) =
                    make_float2(tf32r(oacc[mt][nt][0]), tf32r(oacc[mt][nt][1]));
                *(float2*)(O + qbase + (long long)(row + 8) * DIMN + col) =
                    make_float2(tf32r(oacc[mt][nt][2]), tf32r(oacc[mt][nt][3]));
            }
        }
    }
}

// =====================================================================
// launch
// =====================================================================
extern "C" void kernel_launch(void* const* d_in, const int* in_sizes, int n_in,
                              void* d_out, int out_size)
{
    (void)in_sizes; (void)n_in; (void)out_size;

    const float* x  = (const float*)d_in[0];
    const float* Wq = (const float*)d_in[1];
    const float* Wk = (const float*)d_in[2];
    const float* Wv = (const float*)d_in[3];
    const float* pk = (const float*)d_in[4];
    const float* pv = (const float*)d_in[5];
    const float* Wo = (const float*)d_in[6];
    const float* bo = (const float*)d_in[7];
    float* out = (float*)d_out;

    float *Q, *AO, *keys, *vals, *xk, *xv;
    float *xt, *wqt, *wkt, *wvt, *wot, *pkt, *pvt;
    cudaGetSymbolAddress((void**)&Q, g_Q);
    cudaGetSymbolAddress((void**)&AO, g_AO);
    cudaGetSymbolAddress((void**)&keys, g_keys);
    cudaGetSymbolAddress((void**)&vals, g_vals);
    cudaGetSymbolAddress((void**)&xk, g_xk);
    cudaGetSymbolAddress((void**)&xv, g_xv);
    cudaGetSymbolAddress((void**)&xt, g_xt);
    cudaGetSymbolAddress((void**)&wqt, g_wqt);
    cudaGetSymbolAddress((void**)&wkt, g_wkt);
    cudaGetSymbolAddress((void**)&wvt, g_wvt);
    cudaGetSymbolAddress((void**)&wot, g_wot);
    cudaGetSymbolAddress((void**)&pkt, g_pkt);
    cudaGetSymbolAddress((void**)&pvt, g_pvt);

    // 0) round inputs to tf32 once
    {
        int n4x = (M_TOK * DIMN) / 4;
        round_tf32_kernel<<<(n4x + 255) / 256, 256>>>(x, xt, n4x);
        int n4w = (DIMN * DIMN) / 4;
        round_tf32_kernel<<<(n4w + 255) / 256, 256>>>(Wq, wqt, n4w);
        round_tf32_kernel<<<(n4w + 255) / 256, 256>>>(Wk, wkt, n4w);
        round_tf32_kernel<<<(n4w + 255) / 256, 256>>>(Wv, wvt, n4w);
        round_tf32_kernel<<<(n4w + 255) / 256, 256>>>(Wo, wot, n4w);
        int n4p = (SEQN * KLR) / 4;
        round_tf32_kernel<<<(n4p + 255) / 256, 256>>>(pk, pkt, n4p);
        round_tf32_kernel<<<(n4p + 255) / 256, 256>>>(pv, pvt, n4p);
    }

    cudaFuncSetAttribute(gemm_nt_tf32,
                         cudaFuncAttributeMaxDynamicSharedMemorySize, NT_SMEM);

    // 1) Q projection (4-stage ldmatrix NT) — tf32-rounded output
    dim3 gbig(DIMN / 128, M_TOK / 128);
    gemm_nt_tf32<<<gbig, 256, NT_SMEM>>>(xt, wqt, nullptr, Q,
                                         DIMN, DIMN, DIMN, DIMN, 0, 1);

    // 2) fused sequence projection: xk = pk^T x, xv = pv^T x
    dim3 gproj(DIMN / 128, KLR / 64, BATCHN);
    gemm_tn2_tf32<<<gproj, 256>>>(pkt, pvt, xt, xk, xv, SEQN, KLR, DIMN, DIMN,
                                  (long long)SEQN * DIMN, (long long)KLR * DIMN);

    // 3) keys = xk·Wk^T, vals = xv·Wv^T (rounded, feed attention)
    dim3 gsmall(DIMN / 128, (BATCHN * KLR) / 128);
    gemm_nt_tf32<<<gsmall, 256, NT_SMEM>>>(xk, wkt, nullptr, keys,
                                           DIMN, DIMN, DIMN, DIMN, 0, 1);
    gemm_nt_tf32<<<gsmall, 256, NT_SMEM>>>(xv, wvt, nullptr, vals,
                                           DIMN, DIMN, DIMN, DIMN, 0, 1);

    // 4) fused attention (writes tf32-rounded AO)
    cudaFuncSetAttribute(attn_kernel,
                         cudaFuncAttributeMaxDynamicSharedMemorySize,
                         ATT_SMEM_BYTES);
    dim3 gatt(SEQN / 64, HEADSN, BATCHN);
    attn_kernel<<<gatt, 256, ATT_SMEM_BYTES>>>(Q, keys, vals, AO);

    // 5) output projection + bias (4-stage ldmatrix NT)
    gemm_nt_tf32<<<gbig, 256, NT_SMEM>>>(AO, wot, bo, out,
                                         DIMN, DIMN, DIMN, DIMN, 1, 0);
}